// round 1
// baseline (speedup 1.0000x reference)
#include <cuda_runtime.h>
#include <math.h>

// Problem constants (fixed shapes from reference setup_inputs)
#define BB 8
#define NN 1024
#define MM 1024
#define DD 64
#define EPSF 0.1f
#define INV_EPS 10.0f
#define N_ITER 20

// Scratch (no allocations allowed -> __device__ globals)
__device__ float g_U[BB * NN];
__device__ float g_V[BB * MM];
__device__ float g_xn[BB * NN];
__device__ float g_yn[BB * MM];
__device__ float g_lognu[BB * MM];

// ---------------------------------------------------------------------------
// Init: row norms of x and y, log_nu, zero U/V and cost
// ---------------------------------------------------------------------------
__global__ void sk_init(const float* __restrict__ x, const float* __restrict__ y,
                        const float* __restrict__ w, float* __restrict__ cost) {
    int idx = blockIdx.x * blockDim.x + threadIdx.x;  // 0..8191
    if (idx < BB) cost[idx] = 0.0f;
    if (idx < BB * NN) {
        const float4* xr = (const float4*)(x + (size_t)idx * DD);
        float s = 0.0f;
#pragma unroll
        for (int k = 0; k < DD / 4; k++) {
            float4 v = xr[k];
            s += v.x * v.x + v.y * v.y + v.z * v.z + v.w * v.w;
        }
        g_xn[idx] = s;
        g_U[idx] = 0.0f;
    }
    if (idx < BB * MM) {
        const float4* yr = (const float4*)(y + (size_t)idx * DD);
        float s = 0.0f;
#pragma unroll
        for (int k = 0; k < DD / 4; k++) {
            float4 v = yr[k];
            s += v.x * v.x + v.y * v.y + v.z * v.z + v.w * v.w;
        }
        g_yn[idx] = s;
        g_V[idx] = 0.0f;
        g_lognu[idx] = logf(w[idx] + 1e-8f);
    }
}

// ---------------------------------------------------------------------------
// C[b,i,j] = ||x_i||^2 + ||y_j||^2 - 2 x_i . y_j   (fp32 tiled GEMM, K=64)
// 64x64 tile per block, 16x16 threads, 4x4 micro-tile, K-major shared layout.
// ---------------------------------------------------------------------------
__global__ void sk_gemm(const float* __restrict__ x, const float* __restrict__ y,
                        float* __restrict__ C) {
    __shared__ float Xs[DD][68];  // [k][i], row stride 68 floats (16B-aligned rows)
    __shared__ float Ys[DD][68];  // [k][j]
    int b = blockIdx.z;
    int i0 = blockIdx.y * 64;
    int j0 = blockIdx.x * 64;
    int tid = threadIdx.y * 16 + threadIdx.x;

    const float* xb = x + ((size_t)b * NN + i0) * DD;
    const float* yb = y + ((size_t)b * MM + j0) * DD;
    for (int t = tid; t < 64 * DD; t += 256) {
        int r = t >> 6;       // row within tile
        int d = t & 63;       // feature
        Xs[d][r] = xb[r * DD + d];
        Ys[d][r] = yb[r * DD + d];
    }
    __syncthreads();

    float acc[4][4] = {};
    int ti = threadIdx.y * 4;
    int tj = threadIdx.x * 4;
#pragma unroll
    for (int k = 0; k < DD; k++) {
        float4 a = *(const float4*)&Xs[k][ti];
        float4 bv = *(const float4*)&Ys[k][tj];
        acc[0][0] += a.x * bv.x; acc[0][1] += a.x * bv.y; acc[0][2] += a.x * bv.z; acc[0][3] += a.x * bv.w;
        acc[1][0] += a.y * bv.x; acc[1][1] += a.y * bv.y; acc[1][2] += a.y * bv.z; acc[1][3] += a.y * bv.w;
        acc[2][0] += a.z * bv.x; acc[2][1] += a.z * bv.y; acc[2][2] += a.z * bv.z; acc[2][3] += a.z * bv.w;
        acc[3][0] += a.w * bv.x; acc[3][1] += a.w * bv.y; acc[3][2] += a.w * bv.z; acc[3][3] += a.w * bv.w;
    }

    float yn0 = g_yn[(size_t)b * MM + j0 + tj + 0];
    float yn1 = g_yn[(size_t)b * MM + j0 + tj + 1];
    float yn2 = g_yn[(size_t)b * MM + j0 + tj + 2];
    float yn3 = g_yn[(size_t)b * MM + j0 + tj + 3];
#pragma unroll
    for (int r = 0; r < 4; r++) {
        float xnv = g_xn[(size_t)b * NN + i0 + ti + r];
        float4 o;
        o.x = xnv + yn0 - 2.0f * acc[r][0];
        o.y = xnv + yn1 - 2.0f * acc[r][1];
        o.z = xnv + yn2 - 2.0f * acc[r][2];
        o.w = xnv + yn3 - 2.0f * acc[r][3];
        *(float4*)&C[((size_t)b * NN + i0 + ti + r) * MM + j0 + tj] = o;
    }
}

// ---------------------------------------------------------------------------
// Row pass: U_i = eps*(log_mu - log(sum_j exp((-C_ij + U_i + V_j)/eps) + 1e-6)) + U_i
// One warp per row; 8 rows (one batch) per 256-thread block.
// ---------------------------------------------------------------------------
__global__ void sk_row(const float* __restrict__ C) {
    __shared__ float Vs[MM];
    int rowblock = blockIdx.x;                 // 1024 blocks, 8 rows each
    int b = (rowblock * 8) / NN;
    int tid = threadIdx.x;
    for (int t = tid; t < MM; t += 256) Vs[t] = g_V[b * MM + t];
    __syncthreads();

    int warp = tid >> 5, lane = tid & 31;
    int row = rowblock * 8 + warp;             // global row in [0, B*N)
    float u = g_U[row];
    const float4* cr = (const float4*)(C + (size_t)row * MM);
    const float4* vr = (const float4*)Vs;
    float s = 0.0f;
#pragma unroll
    for (int k = 0; k < MM / 128; k++) {
        int j4 = lane + k * 32;
        float4 c = cr[j4];
        float4 v = vr[j4];
        s += __expf((v.x - c.x + u) * INV_EPS);
        s += __expf((v.y - c.y + u) * INV_EPS);
        s += __expf((v.z - c.z + u) * INV_EPS);
        s += __expf((v.w - c.w + u) * INV_EPS);
    }
#pragma unroll
    for (int o = 16; o; o >>= 1) s += __shfl_xor_sync(0xFFFFFFFFu, s, o);
    if (lane == 0) {
        const float log_mu = logf(1.0f / (float)NN + 1e-8f);
        g_U[row] = EPSF * (log_mu - logf(s + 1e-6f)) + u;
    }
}

// ---------------------------------------------------------------------------
// Col pass: V_j = eps*(log_nu_j - log(sum_i exp((-C_ij + U_i + V_j)/eps) + 1e-6)) + V_j
// 256 threads = 32 columns x 8 row-groups of 128 rows. Coalesced 128B loads.
// ---------------------------------------------------------------------------
__global__ void sk_col(const float* __restrict__ C) {
    __shared__ float Us[NN];
    __shared__ float part[8][33];
    int blk = blockIdx.x;              // B * 32 blocks
    int b = blk >> 5;
    int j0 = (blk & 31) * 32;
    int tid = threadIdx.x;
    for (int t = tid; t < NN; t += 256) Us[t] = g_U[b * NN + t];
    __syncthreads();

    int c = tid & 31, r = tid >> 5;
    int j = j0 + c;
    float v = g_V[b * MM + j];
    const float* cp = C + ((size_t)b * NN + r * 128) * MM + j;
    const float* up = Us + r * 128;
    float s = 0.0f;
#pragma unroll 4
    for (int i = 0; i < 128; i++) {
        float cc = cp[(size_t)i * MM];
        s += __expf((up[i] - cc + v) * INV_EPS);
    }
    part[r][c] = s;
    __syncthreads();
    if (r == 0) {
        float tot = 0.0f;
#pragma unroll
        for (int rr = 0; rr < 8; rr++) tot += part[rr][c];
        g_V[b * MM + j] = EPSF * (g_lognu[b * MM + j] - logf(tot + 1e-6f)) + v;
    }
}

// ---------------------------------------------------------------------------
// Final: pi = exp((-C + U + V)/eps); cost_b = sum_ij pi*C
// ---------------------------------------------------------------------------
__global__ void sk_final(const float* __restrict__ C, float* __restrict__ pi,
                         float* __restrict__ cost) {
    __shared__ float Vs[MM];
    __shared__ float wsum[8];
    int rowblock = blockIdx.x;
    int b = (rowblock * 8) / NN;
    int tid = threadIdx.x;
    for (int t = tid; t < MM; t += 256) Vs[t] = g_V[b * MM + t];
    __syncthreads();

    int warp = tid >> 5, lane = tid & 31;
    int row = rowblock * 8 + warp;
    float u = g_U[row];
    const float4* cr = (const float4*)(C + (size_t)row * MM);
    const float4* vr = (const float4*)Vs;
    float4* pr = (float4*)(pi + (size_t)row * MM);
    float s = 0.0f;
#pragma unroll
    for (int k = 0; k < MM / 128; k++) {
        int j4 = lane + k * 32;
        float4 c = cr[j4];
        float4 v = vr[j4];
        float4 p;
        p.x = __expf((v.x - c.x + u) * INV_EPS);
        p.y = __expf((v.y - c.y + u) * INV_EPS);
        p.z = __expf((v.z - c.z + u) * INV_EPS);
        p.w = __expf((v.w - c.w + u) * INV_EPS);
        pr[j4] = p;
        s += p.x * c.x + p.y * c.y + p.z * c.z + p.w * c.w;
    }
#pragma unroll
    for (int o = 16; o; o >>= 1) s += __shfl_xor_sync(0xFFFFFFFFu, s, o);
    if (lane == 0) wsum[warp] = s;
    __syncthreads();
    if (tid == 0) {
        float tot = 0.0f;
#pragma unroll
        for (int w2 = 0; w2 < 8; w2++) tot += wsum[w2];
        atomicAdd(&cost[b], tot);
    }
}

// ---------------------------------------------------------------------------
// Launch
// Output layout (reference returns (cost, pi, C) concatenated):
//   [0, 8)                      cost  (B,)
//   [8, 8 + B*N*M)              pi    (B,N,M)
//   [8 + B*N*M, 8 + 2*B*N*M)    C     (B,N,M)
// ---------------------------------------------------------------------------
extern "C" void kernel_launch(void* const* d_in, const int* in_sizes, int n_in,
                              void* d_out, int out_size) {
    const float* x = (const float*)d_in[0];
    const float* y = (const float*)d_in[1];
    const float* w = (const float*)d_in[2];
    float* cost = (float*)d_out;
    float* pi = cost + BB;
    float* C = pi + (size_t)BB * NN * MM;

    sk_init<<<32, 256>>>(x, y, w, cost);
    sk_gemm<<<dim3(MM / 64, NN / 64, BB), dim3(16, 16)>>>(x, y, C);
    for (int it = 0; it < N_ITER; it++) {
        sk_row<<<BB * NN / 8, 256>>>(C);
        sk_col<<<BB * MM / 32, 256>>>(C);
    }
    sk_final<<<BB * NN / 8, 256>>>(C, pi, cost);
}

// round 2
// speedup vs baseline: 1.0869x; 1.0869x over previous
#include <cuda_runtime.h>
#include <math.h>

// Problem constants (fixed shapes from reference setup_inputs)
#define BB 8
#define NN 1024
#define MM 1024
#define DD 64
#define EPSF 0.1f
#define INV_EPS 10.0f
#define N_ITER 20

#define ROWS_PER_BLK 16
#define ITER_THREADS 512
// dynamic smem: Vs[MM] + r[ROWS_PER_BLK][MM] + a[ROWS_PER_BLK]
#define SMEM_ITER ((MM + ROWS_PER_BLK * MM + ROWS_PER_BLK) * 4)

// Scratch (no allocations allowed -> __device__ globals)
__device__ float g_U[BB * NN];
__device__ float g_Vb[2][BB * MM];         // double-buffered V state
__device__ float g_cs[N_ITER][BB * MM];    // per-iteration column sums
__device__ float g_xn[BB * NN];
__device__ float g_yn[BB * MM];
__device__ float g_lognu[BB * MM];

// ---------------------------------------------------------------------------
// Init: row norms, log_nu, zero U / V0 / colsum buffers / cost
// ---------------------------------------------------------------------------
__global__ void sk_init(const float* __restrict__ x, const float* __restrict__ y,
                        const float* __restrict__ w, float* __restrict__ cost) {
    int idx = blockIdx.x * blockDim.x + threadIdx.x;  // 0..8191
    if (idx < BB) cost[idx] = 0.0f;
    if (idx < BB * NN) {
        const float4* xr = (const float4*)(x + (size_t)idx * DD);
        float s = 0.0f;
#pragma unroll
        for (int k = 0; k < DD / 4; k++) {
            float4 v = xr[k];
            s += v.x * v.x + v.y * v.y + v.z * v.z + v.w * v.w;
        }
        g_xn[idx] = s;
        g_U[idx] = 0.0f;
    }
    if (idx < BB * MM) {
        const float4* yr = (const float4*)(y + (size_t)idx * DD);
        float s = 0.0f;
#pragma unroll
        for (int k = 0; k < DD / 4; k++) {
            float4 v = yr[k];
            s += v.x * v.x + v.y * v.y + v.z * v.z + v.w * v.w;
        }
        g_yn[idx] = s;
        g_Vb[0][idx] = 0.0f;
        g_lognu[idx] = logf(w[idx] + 1e-8f);
    }
#pragma unroll
    for (int k = 0; k < N_ITER; k++) g_cs[k][idx] = 0.0f;
}

// ---------------------------------------------------------------------------
// C[b,i,j] = ||x_i||^2 + ||y_j||^2 - 2 x_i . y_j   (fp32 tiled GEMM, K=64)
// ---------------------------------------------------------------------------
__global__ void sk_gemm(const float* __restrict__ x, const float* __restrict__ y,
                        float* __restrict__ C) {
    __shared__ float Xs[DD][68];
    __shared__ float Ys[DD][68];
    int b = blockIdx.z;
    int i0 = blockIdx.y * 64;
    int j0 = blockIdx.x * 64;
    int tid = threadIdx.y * 16 + threadIdx.x;

    const float* xb = x + ((size_t)b * NN + i0) * DD;
    const float* yb = y + ((size_t)b * MM + j0) * DD;
    for (int t = tid; t < 64 * DD; t += 256) {
        int r = t >> 6;
        int d = t & 63;
        Xs[d][r] = xb[r * DD + d];
        Ys[d][r] = yb[r * DD + d];
    }
    __syncthreads();

    float acc[4][4] = {};
    int ti = threadIdx.y * 4;
    int tj = threadIdx.x * 4;
#pragma unroll
    for (int k = 0; k < DD; k++) {
        float4 a = *(const float4*)&Xs[k][ti];
        float4 bv = *(const float4*)&Ys[k][tj];
        acc[0][0] += a.x * bv.x; acc[0][1] += a.x * bv.y; acc[0][2] += a.x * bv.z; acc[0][3] += a.x * bv.w;
        acc[1][0] += a.y * bv.x; acc[1][1] += a.y * bv.y; acc[1][2] += a.y * bv.z; acc[1][3] += a.y * bv.w;
        acc[2][0] += a.z * bv.x; acc[2][1] += a.z * bv.y; acc[2][2] += a.z * bv.z; acc[2][3] += a.z * bv.w;
        acc[3][0] += a.w * bv.x; acc[3][1] += a.w * bv.y; acc[3][2] += a.w * bv.z; acc[3][3] += a.w * bv.w;
    }

    float yn0 = g_yn[(size_t)b * MM + j0 + tj + 0];
    float yn1 = g_yn[(size_t)b * MM + j0 + tj + 1];
    float yn2 = g_yn[(size_t)b * MM + j0 + tj + 2];
    float yn3 = g_yn[(size_t)b * MM + j0 + tj + 3];
#pragma unroll
    for (int r = 0; r < 4; r++) {
        float xnv = g_xn[(size_t)b * NN + i0 + ti + r];
        float4 o;
        o.x = xnv + yn0 - 2.0f * acc[r][0];
        o.y = xnv + yn1 - 2.0f * acc[r][1];
        o.z = xnv + yn2 - 2.0f * acc[r][2];
        o.w = xnv + yn3 - 2.0f * acc[r][3];
        *(float4*)&C[((size_t)b * NN + i0 + ti + r) * MM + j0 + tj] = o;
    }
}

// ---------------------------------------------------------------------------
// Fused Sinkhorn iteration: ONE row-major pass over C.
//  Phase 0: V_it = eps*(log_nu - log(colsum_{it-1}+1e-6)) + V_{it-1}  (in smem,
//           recomputed redundantly per block; one block/batch persists it)
//  Phase 1: r_ij = exp((V_j - C_ij + U_i)/eps), rowsum -> U update,
//           a_i = (1/N+1e-8)/(rowsum+1e-6)  [= exp((U'-U)/eps)]
//  Phase 2: colsum_j += sum_i r_ij * a_i  (atomic into g_cs[it])
// Grid: BB*NN/16 = 512 blocks x 512 threads. 16 rows per block.
// ---------------------------------------------------------------------------
__global__ void sk_iter(const float* __restrict__ C, int it) {
    extern __shared__ float sm[];
    float* Vs = sm;                    // [MM]
    float* r = sm + MM;                // [ROWS_PER_BLK][MM]
    float* a_sh = sm + MM + ROWS_PER_BLK * MM;  // [ROWS_PER_BLK]

    const int tid = threadIdx.x;
    const int b = blockIdx.x >> 6;               // 64 blocks per batch
    const int boff = b * MM;

    // ---- Phase 0: build V for this iteration ----
    if (it == 0) {
        for (int t = tid; t < MM; t += ITER_THREADS) Vs[t] = 0.0f;
    } else {
        const float* vold = g_Vb[(it - 1) & 1] + boff;
        const float* cs = g_cs[it - 1] + boff;
        const bool writer = ((blockIdx.x & 63) == 0);
        for (int t = tid; t < MM; t += ITER_THREADS) {
            float vn = EPSF * (g_lognu[boff + t] - __logf(cs[t] + 1e-6f)) + vold[t];
            Vs[t] = vn;
            if (writer) g_Vb[it & 1][boff + t] = vn;
        }
    }
    __syncthreads();

    // ---- Phase 1: row pass ----
    const int warp = tid >> 5, lane = tid & 31;
    const int gr = blockIdx.x * ROWS_PER_BLK + warp;   // global row in [0, B*N)
    const float u = g_U[gr];
    const float4* cr = (const float4*)(C + (size_t)gr * MM);
    const float4* vr = (const float4*)Vs;
    float4* rw = (float4*)(r + warp * MM);
    float s = 0.0f;
#pragma unroll
    for (int k = 0; k < MM / 128; k++) {
        int j4 = lane + 32 * k;
        float4 c = cr[j4];
        float4 v = vr[j4];
        float4 e;
        e.x = __expf((v.x - c.x + u) * INV_EPS);
        e.y = __expf((v.y - c.y + u) * INV_EPS);
        e.z = __expf((v.z - c.z + u) * INV_EPS);
        e.w = __expf((v.w - c.w + u) * INV_EPS);
        rw[j4] = e;
        s += e.x + e.y + e.z + e.w;
    }
#pragma unroll
    for (int o = 16; o; o >>= 1) s += __shfl_xor_sync(0xFFFFFFFFu, s, o);
    if (lane == 0) {
        const float log_mu = logf(1.0f / (float)NN + 1e-8f);   // constant-folded
        const float mu_c = 1.0f / (float)NN + 1e-8f;           // exp(log_mu)
        float rs1 = s + 1e-6f;
        g_U[gr] = EPSF * (log_mu - __logf(rs1)) + u;
        a_sh[warp] = mu_c / rs1;   // exp((U'-U)/eps)
    }
    __syncthreads();

    // ---- Phase 2: column partials ----
    float* csout = g_cs[it] + boff;
#pragma unroll
    for (int k = 0; k < MM / ITER_THREADS; k++) {
        int j = tid + ITER_THREADS * k;
        float p = 0.0f;
#pragma unroll
        for (int w = 0; w < ROWS_PER_BLK; w++) p += r[w * MM + j] * a_sh[w];
        atomicAdd(&csout[j], p);
    }
}

// ---------------------------------------------------------------------------
// Final: V_final from last colsum, pi = exp((-C + U + V)/eps), cost = sum pi*C
// ---------------------------------------------------------------------------
__global__ void sk_final(const float* __restrict__ C, float* __restrict__ pi,
                         float* __restrict__ cost) {
    __shared__ float Vs[MM];
    __shared__ float wsum[8];
    int rowblock = blockIdx.x;                 // 1024 blocks, 8 rows each
    int b = (rowblock * 8) / NN;
    int boff = b * MM;
    int tid = threadIdx.x;
    const float* vold = g_Vb[(N_ITER - 1) & 1] + boff;
    const float* cs = g_cs[N_ITER - 1] + boff;
    for (int t = tid; t < MM; t += 256)
        Vs[t] = EPSF * (g_lognu[boff + t] - __logf(cs[t] + 1e-6f)) + vold[t];
    __syncthreads();

    int warp = tid >> 5, lane = tid & 31;
    int row = rowblock * 8 + warp;
    float u = g_U[row];
    const float4* cr = (const float4*)(C + (size_t)row * MM);
    const float4* vr = (const float4*)Vs;
    float4* pr = (float4*)(pi + (size_t)row * MM);
    float s = 0.0f;
#pragma unroll
    for (int k = 0; k < MM / 128; k++) {
        int j4 = lane + k * 32;
        float4 c = cr[j4];
        float4 v = vr[j4];
        float4 p;
        p.x = __expf((v.x - c.x + u) * INV_EPS);
        p.y = __expf((v.y - c.y + u) * INV_EPS);
        p.z = __expf((v.z - c.z + u) * INV_EPS);
        p.w = __expf((v.w - c.w + u) * INV_EPS);
        pr[j4] = p;
        s += p.x * c.x + p.y * c.y + p.z * c.z + p.w * c.w;
    }
#pragma unroll
    for (int o = 16; o; o >>= 1) s += __shfl_xor_sync(0xFFFFFFFFu, s, o);
    if (lane == 0) wsum[warp] = s;
    __syncthreads();
    if (tid == 0) {
        float tot = 0.0f;
#pragma unroll
        for (int w2 = 0; w2 < 8; w2++) tot += wsum[w2];
        atomicAdd(&cost[b], tot);
    }
}

// ---------------------------------------------------------------------------
// Launch
// Output layout: [0,8) cost | [8, 8+B*N*M) pi | then C
// ---------------------------------------------------------------------------
extern "C" void kernel_launch(void* const* d_in, const int* in_sizes, int n_in,
                              void* d_out, int out_size) {
    const float* x = (const float*)d_in[0];
    const float* y = (const float*)d_in[1];
    const float* w = (const float*)d_in[2];
    float* cost = (float*)d_out;
    float* pi = cost + BB;
    float* C = pi + (size_t)BB * NN * MM;

    cudaFuncSetAttribute(sk_iter, cudaFuncAttributeMaxDynamicSharedMemorySize,
                         SMEM_ITER);

    sk_init<<<32, 256>>>(x, y, w, cost);
    sk_gemm<<<dim3(MM / 64, NN / 64, BB), dim3(16, 16)>>>(x, y, C);
    for (int it = 0; it < N_ITER; it++) {
        sk_iter<<<BB * NN / ROWS_PER_BLK, ITER_THREADS, SMEM_ITER>>>(C, it);
    }
    sk_final<<<BB * NN / 8, 256>>>(C, pi, cost);
}

// round 3
// speedup vs baseline: 1.2612x; 1.1604x over previous
#include <cuda_runtime.h>
#include <math.h>

// Problem constants (fixed shapes from reference setup_inputs)
#define BB 8
#define NN 1024
#define MM 1024
#define DD 64
#define EPSF 0.1f
#define INV_EPS 10.0f
#define N_ITER 20

// K_SCALE = (1/eps) * log2(e): exp(z/eps) == exp2(z * K_SCALE)
#define K_SCALE 14.426950408889634f
// log2(1/1024 + 1e-8)
#define LOGMU2 (-9.9999852284f)

#define ROWS_PER_BLK 16
#define ITER_THREADS 512
// dynamic smem: Vs[MM] + r[ROWS_PER_BLK][MM] + a_pack[ROWS_PER_BLK] (ull)
#define SMEM_ITER ((MM + ROWS_PER_BLK * MM) * 4 + ROWS_PER_BLK * 8)

typedef unsigned long long ull;

// ---- packed f32x2 helpers (sm_103a) ----
__device__ __forceinline__ ull pack2(float lo, float hi) {
    ull r;
    asm("mov.b64 %0, {%1, %2};" : "=l"(r) : "f"(lo), "f"(hi));
    return r;
}
__device__ __forceinline__ void unpack2(float& lo, float& hi, ull v) {
    asm("mov.b64 {%0, %1}, %2;" : "=f"(lo), "=f"(hi) : "l"(v));
}
__device__ __forceinline__ ull add2(ull a, ull b) {
    ull r;
    asm("add.rn.f32x2 %0, %1, %2;" : "=l"(r) : "l"(a), "l"(b));
    return r;
}
__device__ __forceinline__ ull fma2(ull a, ull b, ull c) {
    ull r;
    asm("fma.rn.f32x2 %0, %1, %2, %3;" : "=l"(r) : "l"(a), "l"(b), "l"(c));
    return r;
}
__device__ __forceinline__ float ex2(float x) {
    float r;
    asm("ex2.approx.f32 %0, %1;" : "=f"(r) : "f"(x));
    return r;
}

// Scratch (no allocations allowed -> __device__ globals)
__device__ float g_Cs[(size_t)BB * NN * MM];  // C' = -C * K_SCALE
__device__ float g_U[BB * NN];                // scaled: U * K_SCALE
__device__ float g_Vb[2][BB * MM];            // scaled V, double-buffered
__device__ float g_cs[N_ITER][BB * MM];       // per-iteration column sums
__device__ float g_xn[BB * NN];
__device__ float g_yn[BB * MM];
__device__ float g_lognu2[BB * MM];           // log2(nu + 1e-8)

// ---------------------------------------------------------------------------
// Init
// ---------------------------------------------------------------------------
__global__ void sk_init(const float* __restrict__ x, const float* __restrict__ y,
                        const float* __restrict__ w, float* __restrict__ cost) {
    int idx = blockIdx.x * blockDim.x + threadIdx.x;  // 0..8191
    if (idx < BB) cost[idx] = 0.0f;
    if (idx < BB * NN) {
        const float4* xr = (const float4*)(x + (size_t)idx * DD);
        float s = 0.0f;
#pragma unroll
        for (int k = 0; k < DD / 4; k++) {
            float4 v = xr[k];
            s += v.x * v.x + v.y * v.y + v.z * v.z + v.w * v.w;
        }
        g_xn[idx] = s;
        g_U[idx] = 0.0f;
    }
    if (idx < BB * MM) {
        const float4* yr = (const float4*)(y + (size_t)idx * DD);
        float s = 0.0f;
#pragma unroll
        for (int k = 0; k < DD / 4; k++) {
            float4 v = yr[k];
            s += v.x * v.x + v.y * v.y + v.z * v.z + v.w * v.w;
        }
        g_yn[idx] = s;
        g_Vb[0][idx] = 0.0f;
        g_lognu2[idx] = __log2f(w[idx] + 1e-8f);
    }
#pragma unroll
    for (int k = 0; k < N_ITER; k++) g_cs[k][idx] = 0.0f;
}

// ---------------------------------------------------------------------------
// GEMM: C = ||x||^2 + ||y||^2 - 2 x.y ; also C' = -C*K_SCALE  (f32x2 packed)
// ---------------------------------------------------------------------------
__global__ void sk_gemm(const float* __restrict__ x, const float* __restrict__ y,
                        float* __restrict__ C) {
    __shared__ float Xs[DD][68];  // [k][i], 272B rows (16B aligned)
    __shared__ float Ys[DD][68];
    int b = blockIdx.z;
    int i0 = blockIdx.y * 64;
    int j0 = blockIdx.x * 64;
    int tid = threadIdx.y * 16 + threadIdx.x;

    const float* xb = x + ((size_t)b * NN + i0) * DD;
    const float* yb = y + ((size_t)b * MM + j0) * DD;
    for (int t = tid; t < 64 * DD; t += 256) {
        int r = t >> 6;
        int d = t & 63;
        Xs[d][r] = xb[r * DD + d];
        Ys[d][r] = yb[r * DD + d];
    }
    __syncthreads();

    int ti = threadIdx.y * 4;
    int tj = threadIdx.x * 4;
    ull acc2[4][2];
#pragma unroll
    for (int r = 0; r < 4; r++) { acc2[r][0] = 0ull; acc2[r][1] = 0ull; }

#pragma unroll
    for (int k = 0; k < DD; k++) {
        float4 a4 = *(const float4*)&Xs[k][ti];
        ulonglong2 b2 = *(const ulonglong2*)&Ys[k][tj];
        ull a0 = pack2(a4.x, a4.x);
        ull a1 = pack2(a4.y, a4.y);
        ull a2_ = pack2(a4.z, a4.z);
        ull a3 = pack2(a4.w, a4.w);
        acc2[0][0] = fma2(a0, b2.x, acc2[0][0]);
        acc2[0][1] = fma2(a0, b2.y, acc2[0][1]);
        acc2[1][0] = fma2(a1, b2.x, acc2[1][0]);
        acc2[1][1] = fma2(a1, b2.y, acc2[1][1]);
        acc2[2][0] = fma2(a2_, b2.x, acc2[2][0]);
        acc2[2][1] = fma2(a2_, b2.y, acc2[2][1]);
        acc2[3][0] = fma2(a3, b2.x, acc2[3][0]);
        acc2[3][1] = fma2(a3, b2.y, acc2[3][1]);
    }

    float yn0 = g_yn[(size_t)b * MM + j0 + tj + 0];
    float yn1 = g_yn[(size_t)b * MM + j0 + tj + 1];
    float yn2 = g_yn[(size_t)b * MM + j0 + tj + 2];
    float yn3 = g_yn[(size_t)b * MM + j0 + tj + 3];
#pragma unroll
    for (int r = 0; r < 4; r++) {
        float a0, a1, a2v, a3;
        unpack2(a0, a1, acc2[r][0]);
        unpack2(a2v, a3, acc2[r][1]);
        float xnv = g_xn[(size_t)b * NN + i0 + ti + r];
        size_t off = ((size_t)b * NN + i0 + ti + r) * MM + j0 + tj;
        float4 o;
        o.x = xnv + yn0 - 2.0f * a0;
        o.y = xnv + yn1 - 2.0f * a1;
        o.z = xnv + yn2 - 2.0f * a2v;
        o.w = xnv + yn3 - 2.0f * a3;
        *(float4*)&C[off] = o;
        float4 os;
        os.x = -o.x * K_SCALE;
        os.y = -o.y * K_SCALE;
        os.z = -o.z * K_SCALE;
        os.w = -o.w * K_SCALE;
        *(float4*)&g_Cs[off] = os;
    }
}

// ---------------------------------------------------------------------------
// Fused Sinkhorn iteration (scaled log2 domain), one row-major pass over C'.
// ---------------------------------------------------------------------------
__global__ void sk_iter(int it) {
    extern __shared__ float sm[];
    float* Vs = sm;                                  // [MM] scaled V
    float* r = sm + MM;                              // [16][MM]
    ull* a_pk = (ull*)(sm + MM + ROWS_PER_BLK * MM); // [16] packed {a,a}

    const int tid = threadIdx.x;
    const int b = blockIdx.x >> 6;  // 64 blocks per batch
    const int boff = b * MM;

    // ---- Phase 0: build scaled V for this iteration ----
    if (it == 0) {
        for (int t = tid; t < MM; t += ITER_THREADS) Vs[t] = 0.0f;
    } else {
        const float* vold = g_Vb[(it - 1) & 1] + boff;
        const float* cs = g_cs[it - 1] + boff;
        const bool writer = ((blockIdx.x & 63) == 0);
        for (int t = tid; t < MM; t += ITER_THREADS) {
            float vn = vold[t] + g_lognu2[boff + t] - __log2f(cs[t] + 1e-6f);
            Vs[t] = vn;
            if (writer) g_Vb[it & 1][boff + t] = vn;
        }
    }
    __syncthreads();

    // ---- Phase 1: r = exp2(c' + v + u), rowsum -> U update ----
    const int warp = tid >> 5, lane = tid & 31;
    const int gr = blockIdx.x * ROWS_PER_BLK + warp;
    const float u_s = g_U[gr];
    const ull u2 = pack2(u_s, u_s);
    const ulonglong2* cr = (const ulonglong2*)(g_Cs + (size_t)gr * MM);
    const ulonglong2* vr = (const ulonglong2*)Vs;
    ulonglong2* rw = (ulonglong2*)(r + warp * MM);
    ull s01 = 0ull, s23 = 0ull;
#pragma unroll
    for (int k = 0; k < MM / 128; k++) {
        int j4 = lane + 32 * k;
        ulonglong2 c = cr[j4];
        ulonglong2 v = vr[j4];
        ull t01 = add2(add2(c.x, v.x), u2);
        ull t23 = add2(add2(c.y, v.y), u2);
        float e0, e1, e2, e3;
        unpack2(e0, e1, t01);
        unpack2(e2, e3, t23);
        e0 = ex2(e0); e1 = ex2(e1); e2 = ex2(e2); e3 = ex2(e3);
        ulonglong2 ev;
        ev.x = pack2(e0, e1);
        ev.y = pack2(e2, e3);
        rw[j4] = ev;
        s01 = add2(s01, ev.x);
        s23 = add2(s23, ev.y);
    }
    ull st = add2(s01, s23);
    float sl, sh;
    unpack2(sl, sh, st);
    float s = sl + sh;
#pragma unroll
    for (int o = 16; o; o >>= 1) s += __shfl_xor_sync(0xFFFFFFFFu, s, o);
    if (lane == 0) {
        float lg = __log2f(s + 1e-6f);
        g_U[gr] = u_s + LOGMU2 - lg;
        float a = ex2(LOGMU2 - lg);  // exp((U'-U)/eps)
        a_pk[warp] = pack2(a, a);
    }
    __syncthreads();

    // ---- Phase 2: column partials (float4 per thread, 256 active) ----
    if (tid < MM / 4) {
        float* csout = g_cs[it] + boff;
        ull p01 = 0ull, p23 = 0ull;
#pragma unroll
        for (int w = 0; w < ROWS_PER_BLK; w++) {
            ull a2v = a_pk[w];
            ulonglong2 rr = *(const ulonglong2*)(r + w * MM + tid * 4);
            p01 = fma2(rr.x, a2v, p01);
            p23 = fma2(rr.y, a2v, p23);
        }
        float p0, p1, p2, p3;
        unpack2(p0, p1, p01);
        unpack2(p2, p3, p23);
        atomicAdd(&csout[tid * 4 + 0], p0);
        atomicAdd(&csout[tid * 4 + 1], p1);
        atomicAdd(&csout[tid * 4 + 2], p2);
        atomicAdd(&csout[tid * 4 + 3], p3);
    }
}

// ---------------------------------------------------------------------------
// Final: V from last colsum, pi = exp2(c' + u + v), cost = sum pi*C
// ---------------------------------------------------------------------------
__global__ void sk_final(const float* __restrict__ C, float* __restrict__ pi,
                         float* __restrict__ cost) {
    __shared__ float Vs[MM];
    __shared__ float wsum[8];
    int rowblock = blockIdx.x;  // 1024 blocks, 8 rows each
    int b = (rowblock * 8) / NN;
    int boff = b * MM;
    int tid = threadIdx.x;
    const float* vold = g_Vb[(N_ITER - 1) & 1] + boff;
    const float* cs = g_cs[N_ITER - 1] + boff;
    for (int t = tid; t < MM; t += 256)
        Vs[t] = vold[t] + g_lognu2[boff + t] - __log2f(cs[t] + 1e-6f);
    __syncthreads();

    int warp = tid >> 5, lane = tid & 31;
    int row = rowblock * 8 + warp;
    float u_s = g_U[row];
    ull u2 = pack2(u_s, u_s);
    const ulonglong2* cr = (const ulonglong2*)(g_Cs + (size_t)row * MM);
    const float4* cu = (const float4*)(C + (size_t)row * MM);
    const ulonglong2* vr = (const ulonglong2*)Vs;
    float4* pr = (float4*)(pi + (size_t)row * MM);
    float s = 0.0f;
#pragma unroll
    for (int k = 0; k < MM / 128; k++) {
        int j4 = lane + k * 32;
        ulonglong2 c = cr[j4];
        ulonglong2 v = vr[j4];
        float4 cc = cu[j4];
        ull t01 = add2(add2(c.x, v.x), u2);
        ull t23 = add2(add2(c.y, v.y), u2);
        float e0, e1, e2, e3;
        unpack2(e0, e1, t01);
        unpack2(e2, e3, t23);
        float4 p;
        p.x = ex2(e0); p.y = ex2(e1); p.z = ex2(e2); p.w = ex2(e3);
        pr[j4] = p;
        s += p.x * cc.x + p.y * cc.y + p.z * cc.z + p.w * cc.w;
    }
#pragma unroll
    for (int o = 16; o; o >>= 1) s += __shfl_xor_sync(0xFFFFFFFFu, s, o);
    if (lane == 0) wsum[warp] = s;
    __syncthreads();
    if (tid == 0) {
        float tot = 0.0f;
#pragma unroll
        for (int w2 = 0; w2 < 8; w2++) tot += wsum[w2];
        atomicAdd(&cost[b], tot);
    }
}

// ---------------------------------------------------------------------------
// Launch. Output: [0,8) cost | [8, 8+B*N*M) pi | then C
// ---------------------------------------------------------------------------
extern "C" void kernel_launch(void* const* d_in, const int* in_sizes, int n_in,
                              void* d_out, int out_size) {
    const float* x = (const float*)d_in[0];
    const float* y = (const float*)d_in[1];
    const float* w = (const float*)d_in[2];
    float* cost = (float*)d_out;
    float* pi = cost + BB;
    float* C = pi + (size_t)BB * NN * MM;

    cudaFuncSetAttribute(sk_iter, cudaFuncAttributeMaxDynamicSharedMemorySize,
                         SMEM_ITER);

    sk_init<<<32, 256>>>(x, y, w, cost);
    sk_gemm<<<dim3(MM / 64, NN / 64, BB), dim3(16, 16)>>>(x, y, C);
    for (int it = 0; it < N_ITER; it++) {
        sk_iter<<<BB * NN / ROWS_PER_BLK, ITER_THREADS, SMEM_ITER>>>(it);
    }
    sk_final<<<BB * NN / 8, 256>>>(C, pi, cost);
}

// round 4
// speedup vs baseline: 1.7572x; 1.3933x over previous
#include <cuda_runtime.h>
#include <cuda_bf16.h>
#include <math.h>

// Problem constants (fixed shapes from reference setup_inputs)
#define BB 8
#define NN 1024
#define MM 1024
#define DD 64
#define N_ITER 20

// K_SCALE = (1/eps) * log2(e): exp(z/eps) == exp2(z * K_SCALE)
#define K_SCALE 14.426950408889634f
// log2(1/1024 + 1e-8)
#define LOGMU2 (-9.9999852284f)

#define NBLK 148
#define NTHR 1024
#define MAXROWS 56

// dynamic smem (floats): Vs[2][1024] | lognu[2][1024] | a[64] | r bf16[MAXROWS][1024]
#define SMEM_PERSIST ((2048 + 2048 + 64) * 4 + MAXROWS * MM * 2)

typedef unsigned long long ull;

// ---- packed f32x2 helpers (sm_103a) ----
__device__ __forceinline__ ull pack2(float lo, float hi) {
    ull r;
    asm("mov.b64 %0, {%1, %2};" : "=l"(r) : "f"(lo), "f"(hi));
    return r;
}
__device__ __forceinline__ void unpack2(float& lo, float& hi, ull v) {
    asm("mov.b64 {%0, %1}, %2;" : "=f"(lo), "=f"(hi) : "l"(v));
}
__device__ __forceinline__ ull add2(ull a, ull b) {
    ull r;
    asm("add.rn.f32x2 %0, %1, %2;" : "=l"(r) : "l"(a), "l"(b));
    return r;
}
__device__ __forceinline__ ull fma2(ull a, ull b, ull c) {
    ull r;
    asm("fma.rn.f32x2 %0, %1, %2, %3;" : "=l"(r) : "l"(a), "l"(b), "l"(c));
    return r;
}
__device__ __forceinline__ float ex2(float x) {
    float r;
    asm("ex2.approx.f32 %0, %1;" : "=f"(r) : "f"(x));
    return r;
}

// Scratch (no allocations allowed -> __device__ globals)
__device__ float g_cs[N_ITER][BB * MM];  // per-iteration column sums
__device__ int g_barc[N_ITER];           // per-iteration barrier counters
__device__ float g_xn[BB * NN];
__device__ float g_yn[BB * MM];
__device__ float g_lognu2[BB * MM];      // log2(nu + 1e-8)

// ---------------------------------------------------------------------------
// Init
// ---------------------------------------------------------------------------
__global__ void sk_init(const float* __restrict__ x, const float* __restrict__ y,
                        const float* __restrict__ w, float* __restrict__ cost) {
    int idx = blockIdx.x * blockDim.x + threadIdx.x;  // 0..8191
    if (idx < BB) cost[idx] = 0.0f;
    if (idx < N_ITER) g_barc[idx] = 0;
    if (idx < BB * NN) {
        const float4* xr = (const float4*)(x + (size_t)idx * DD);
        float s = 0.0f;
#pragma unroll
        for (int k = 0; k < DD / 4; k++) {
            float4 v = xr[k];
            s += v.x * v.x + v.y * v.y + v.z * v.z + v.w * v.w;
        }
        g_xn[idx] = s;
    }
    if (idx < BB * MM) {
        const float4* yr = (const float4*)(y + (size_t)idx * DD);
        float s = 0.0f;
#pragma unroll
        for (int k = 0; k < DD / 4; k++) {
            float4 v = yr[k];
            s += v.x * v.x + v.y * v.y + v.z * v.z + v.w * v.w;
        }
        g_yn[idx] = s;
        g_lognu2[idx] = __log2f(w[idx] + 1e-8f);
    }
#pragma unroll
    for (int k = 0; k < N_ITER; k++) g_cs[k][idx] = 0.0f;
}

// ---------------------------------------------------------------------------
// GEMM: C = ||x||^2 + ||y||^2 - 2 x.y  (fp32, f32x2 packed FMA)
// ---------------------------------------------------------------------------
__global__ void sk_gemm(const float* __restrict__ x, const float* __restrict__ y,
                        float* __restrict__ C) {
    __shared__ float Xs[DD][68];
    __shared__ float Ys[DD][68];
    int b = blockIdx.z;
    int i0 = blockIdx.y * 64;
    int j0 = blockIdx.x * 64;
    int tid = threadIdx.y * 16 + threadIdx.x;

    const float* xb = x + ((size_t)b * NN + i0) * DD;
    const float* yb = y + ((size_t)b * MM + j0) * DD;
    for (int t = tid; t < 64 * DD; t += 256) {
        int r = t >> 6;
        int d = t & 63;
        Xs[d][r] = xb[r * DD + d];
        Ys[d][r] = yb[r * DD + d];
    }
    __syncthreads();

    int ti = threadIdx.y * 4;
    int tj = threadIdx.x * 4;
    ull acc2[4][2];
#pragma unroll
    for (int r = 0; r < 4; r++) { acc2[r][0] = 0ull; acc2[r][1] = 0ull; }

#pragma unroll
    for (int k = 0; k < DD; k++) {
        float4 a4 = *(const float4*)&Xs[k][ti];
        ulonglong2 b2 = *(const ulonglong2*)&Ys[k][tj];
        ull a0 = pack2(a4.x, a4.x);
        ull a1 = pack2(a4.y, a4.y);
        ull a2_ = pack2(a4.z, a4.z);
        ull a3 = pack2(a4.w, a4.w);
        acc2[0][0] = fma2(a0, b2.x, acc2[0][0]);
        acc2[0][1] = fma2(a0, b2.y, acc2[0][1]);
        acc2[1][0] = fma2(a1, b2.x, acc2[1][0]);
        acc2[1][1] = fma2(a1, b2.y, acc2[1][1]);
        acc2[2][0] = fma2(a2_, b2.x, acc2[2][0]);
        acc2[2][1] = fma2(a2_, b2.y, acc2[2][1]);
        acc2[3][0] = fma2(a3, b2.x, acc2[3][0]);
        acc2[3][1] = fma2(a3, b2.y, acc2[3][1]);
    }

    float yn0 = g_yn[(size_t)b * MM + j0 + tj + 0];
    float yn1 = g_yn[(size_t)b * MM + j0 + tj + 1];
    float yn2 = g_yn[(size_t)b * MM + j0 + tj + 2];
    float yn3 = g_yn[(size_t)b * MM + j0 + tj + 3];
#pragma unroll
    for (int r = 0; r < 4; r++) {
        float a0, a1, a2v, a3;
        unpack2(a0, a1, acc2[r][0]);
        unpack2(a2v, a3, acc2[r][1]);
        float xnv = g_xn[(size_t)b * NN + i0 + ti + r];
        size_t off = ((size_t)b * NN + i0 + ti + r) * MM + j0 + tj;
        float4 o;
        o.x = xnv + yn0 - 2.0f * a0;
        o.y = xnv + yn1 - 2.0f * a1;
        o.z = xnv + yn2 - 2.0f * a2v;
        o.w = xnv + yn3 - 2.0f * a3;
        *(float4*)&C[off] = o;
    }
}

// ---------------------------------------------------------------------------
// Grid barrier over NBLK co-resident blocks (per-iteration counter)
// ---------------------------------------------------------------------------
__device__ __forceinline__ void grid_barrier(int it) {
    __threadfence();
    __syncthreads();
    if (threadIdx.x == 0) {
        atomicAdd(&g_barc[it], 1);
        while (*((volatile int*)&g_barc[it]) < NBLK) __nanosleep(64);
    }
    __syncthreads();
}

// ---------------------------------------------------------------------------
// Phase A row: r_j = exp2(C_j*(-K) + v_j + u), rowsum -> U update + a.
// Warp-collective for one row. Stores r as bf16 into rrow (1024 bf16).
// ---------------------------------------------------------------------------
__device__ __forceinline__ void rowA(const float* __restrict__ Crow,
                                     const float* __restrict__ vseg,
                                     __nv_bfloat162* __restrict__ rrow,
                                     int lane, float& u, float* a_slot) {
    const ull u2 = pack2(u, u);
    const ull nk2 = pack2(-K_SCALE, -K_SCALE);
    const ulonglong2* cr = (const ulonglong2*)Crow;
    const ulonglong2* vr = (const ulonglong2*)vseg;
    uint2* rw = (uint2*)rrow;
    float s0 = 0.f, s1 = 0.f, s2 = 0.f, s3 = 0.f;
#pragma unroll
    for (int k = 0; k < MM / 128; k++) {
        int j4 = lane + 32 * k;
        ulonglong2 c = cr[j4];
        ulonglong2 v = vr[j4];
        ull t01 = fma2(c.x, nk2, add2(v.x, u2));
        ull t23 = fma2(c.y, nk2, add2(v.y, u2));
        float e0, e1, e2, e3;
        unpack2(e0, e1, t01);
        unpack2(e2, e3, t23);
        e0 = ex2(e0); e1 = ex2(e1); e2 = ex2(e2); e3 = ex2(e3);
        __nv_bfloat162 b01 = __floats2bfloat162_rn(e0, e1);
        __nv_bfloat162 b23 = __floats2bfloat162_rn(e2, e3);
        uint2 st;
        st.x = *reinterpret_cast<unsigned*>(&b01);
        st.y = *reinterpret_cast<unsigned*>(&b23);
        rw[j4] = st;  // covers bf16 columns [4*j4, 4*j4+4)
        s0 += e0; s1 += e1; s2 += e2; s3 += e3;
    }
    float s = (s0 + s1) + (s2 + s3);
#pragma unroll
    for (int o = 16; o; o >>= 1) s += __shfl_xor_sync(0xFFFFFFFFu, s, o);
    float unew = 0.f;
    if (lane == 0) {
        float lg = __log2f(s + 1e-6f);
        unew = u + LOGMU2 - lg;
        *a_slot = ex2(LOGMU2 - lg);  // exp((U'-U)/eps)
    }
    u = __shfl_sync(0xFFFFFFFFu, unew, 0);
}

// ---------------------------------------------------------------------------
// Final row: pi = exp2(C*(-K) + v + u), cost partial = sum pi*C
// ---------------------------------------------------------------------------
__device__ __forceinline__ void rowFinal(const float* __restrict__ Crow,
                                         const float* __restrict__ vseg,
                                         float* __restrict__ pirow,
                                         int lane, float u, float* cost_b) {
    const ull u2 = pack2(u, u);
    const ull nk2 = pack2(-K_SCALE, -K_SCALE);
    const float4* cf = (const float4*)Crow;
    const ulonglong2* vr = (const ulonglong2*)vseg;
    float4* pr = (float4*)pirow;
    float s = 0.f;
#pragma unroll
    for (int k = 0; k < MM / 128; k++) {
        int j4 = lane + 32 * k;
        float4 c = cf[j4];
        ulonglong2 v = vr[j4];
        ull c01 = pack2(c.x, c.y);
        ull c23 = pack2(c.z, c.w);
        ull t01 = fma2(c01, nk2, add2(v.x, u2));
        ull t23 = fma2(c23, nk2, add2(v.y, u2));
        float e0, e1, e2, e3;
        unpack2(e0, e1, t01);
        unpack2(e2, e3, t23);
        float4 p;
        p.x = ex2(e0); p.y = ex2(e1); p.z = ex2(e2); p.w = ex2(e3);
        pr[j4] = p;
        s = fmaf(p.x, c.x, s);
        s = fmaf(p.y, c.y, s);
        s = fmaf(p.z, c.z, s);
        s = fmaf(p.w, c.w, s);
    }
#pragma unroll
    for (int o = 16; o; o >>= 1) s += __shfl_xor_sync(0xFFFFFFFFu, s, o);
    if (lane == 0) atomicAdd(cost_b, s);
}

// ---------------------------------------------------------------------------
// Persistent kernel: all 20 Sinkhorn iterations + final pi/cost.
// 148 blocks x 1024 threads, one block per SM, block owns rows [r0, r1).
// ---------------------------------------------------------------------------
__global__ void __launch_bounds__(NTHR, 1)
sk_persist(const float* __restrict__ C, float* __restrict__ pi,
           float* __restrict__ cost) {
    extern __shared__ float sm[];
    float* Vs = sm;                                   // [2][1024]
    float* lognu_sm = sm + 2048;                      // [2][1024]
    float* a_sm = sm + 4096;                          // [64]
    __nv_bfloat162* r_sm = (__nv_bfloat162*)(sm + 4160);  // [MAXROWS][512]

    const int blk = blockIdx.x;
    const int tid = threadIdx.x;
    const int r0 = (blk * BB * NN) / NBLK;
    const int r1 = ((blk + 1) * BB * NN) / NBLK;
    const int nr = r1 - r0;                       // 55 or 56
    const int b0 = r0 >> 10;
    const int bLast = (r1 - 1) >> 10;
    const int nseg = (bLast > b0) ? 2 : 1;
    const int nsplit = (nseg == 2) ? (((b0 + 1) << 10) - r0) : nr;

    // Load lognu segments; V = 0
    for (int s2 = 0; s2 < nseg; s2++) {
        int bo = (b0 + s2) << 10;
        for (int j = tid; j < MM; j += NTHR) {
            lognu_sm[s2 * MM + j] = g_lognu2[bo + j];
            Vs[s2 * MM + j] = 0.0f;
        }
    }
    __syncthreads();

    const int warp = tid >> 5, lane = tid & 31;
    const int row0 = r0 + warp;
    const int row1 = r0 + 32 + warp;
    const bool has1 = (32 + warp) < nr;
    float u0 = 0.0f, u1 = 0.0f;

    // Phase-B mapping: 2 row-groups x 512 threads; thread covers bf16x2 col pair j2
    const int grp = tid >> 9;                // 0 or 1
    const int j2 = tid & 511;                // column-pair index (cols 2j2, 2j2+1)
    const int nrh = nr >> 1;
    const int prow0 = grp ? nrh : 0;
    const int prow1 = grp ? nr : nrh;

    for (int it = 0; it < N_ITER; it++) {
        // ---- Phase 0: local V update from previous colsum ----
        if (it > 0) {
            for (int s2 = 0; s2 < nseg; s2++) {
                int bo = (b0 + s2) << 10;
                const float* cs = g_cs[it - 1] + bo;
                for (int j = tid; j < MM; j += NTHR)
                    Vs[s2 * MM + j] += lognu_sm[s2 * MM + j] - __log2f(cs[j] + 1e-6f);
            }
            __syncthreads();
        }

        // ---- Phase A: rows (warp-per-row, up to 2 rows/warp) ----
        rowA(C + (size_t)row0 * MM, Vs + ((row0 >> 10) - b0) * MM,
             r_sm + (size_t)warp * 512, lane, u0, a_sm + warp);
        if (has1)
            rowA(C + (size_t)row1 * MM, Vs + ((row1 >> 10) - b0) * MM,
                 r_sm + (size_t)(warp + 32) * 512, lane, u1, a_sm + warp + 32);
        __syncthreads();

        // ---- Phase B: column partials from bf16 r, scaled by a ----
        {
            float acc0x = 0.f, acc0y = 0.f, acc1x = 0.f, acc1y = 0.f;
            const int e0r = min(prow1, nsplit);
            for (int rl = prow0; rl < e0r; rl++) {
                float2 rv = __bfloat1622float2(r_sm[(size_t)rl * 512 + j2]);
                float a = a_sm[rl];
                acc0x = fmaf(rv.x, a, acc0x);
                acc0y = fmaf(rv.y, a, acc0y);
            }
            const int s1r = max(prow0, nsplit);
            for (int rl = s1r; rl < prow1; rl++) {
                float2 rv = __bfloat1622float2(r_sm[(size_t)rl * 512 + j2]);
                float a = a_sm[rl];
                acc1x = fmaf(rv.x, a, acc1x);
                acc1y = fmaf(rv.y, a, acc1y);
            }
            if (e0r > prow0) {
                float* csb0 = g_cs[it] + (b0 << 10);
                atomicAdd(&csb0[2 * j2 + 0], acc0x);
                atomicAdd(&csb0[2 * j2 + 1], acc0y);
            }
            if (prow1 > s1r) {
                float* csb1 = g_cs[it] + ((b0 + 1) << 10);
                atomicAdd(&csb1[2 * j2 + 0], acc1x);
                atomicAdd(&csb1[2 * j2 + 1], acc1y);
            }
        }

        grid_barrier(it);
    }

    // ---- Final: V update from cs[N_ITER-1], then pi + cost ----
    for (int s2 = 0; s2 < nseg; s2++) {
        int bo = (b0 + s2) << 10;
        const float* cs = g_cs[N_ITER - 1] + bo;
        for (int j = tid; j < MM; j += NTHR)
            Vs[s2 * MM + j] += lognu_sm[s2 * MM + j] - __log2f(cs[j] + 1e-6f);
    }
    __syncthreads();

    rowFinal(C + (size_t)row0 * MM, Vs + ((row0 >> 10) - b0) * MM,
             pi + (size_t)row0 * MM, lane, u0, &cost[row0 >> 10]);
    if (has1)
        rowFinal(C + (size_t)row1 * MM, Vs + ((row1 >> 10) - b0) * MM,
                 pi + (size_t)row1 * MM, lane, u1, &cost[row1 >> 10]);
}

// ---------------------------------------------------------------------------
// Launch. Output: [0,8) cost | [8, 8+B*N*M) pi | then C
// ---------------------------------------------------------------------------
extern "C" void kernel_launch(void* const* d_in, const int* in_sizes, int n_in,
                              void* d_out, int out_size) {
    const float* x = (const float*)d_in[0];
    const float* y = (const float*)d_in[1];
    const float* w = (const float*)d_in[2];
    float* cost = (float*)d_out;
    float* pi = cost + BB;
    float* C = pi + (size_t)BB * NN * MM;

    cudaFuncSetAttribute(sk_persist, cudaFuncAttributeMaxDynamicSharedMemorySize,
                         SMEM_PERSIST);

    sk_init<<<32, 256>>>(x, y, w, cost);
    sk_gemm<<<dim3(MM / 64, NN / 64, BB), dim3(16, 16)>>>(x, y, C);
    sk_persist<<<NBLK, NTHR, SMEM_PERSIST>>>(C, pi, cost);
}